// round 13
// baseline (speedup 1.0000x reference)
#include <cuda_runtime.h>
#include <cuda_fp16.h>
#include <cuda_bf16.h>

// Problem constants
#define B    8
#define HIN  256
#define WIN  256
#define CV4  16      // C/4 channel chunks per pixel (C=64)
#define HP   64
#define WP   64

// 4 MB pooled averages in fp16 — static device scratch
__device__ uint2 g_pooled[B * HP * WP * CV4];

__device__ __forceinline__ void acc4(float4& a, const float4 v) {
    a.x += v.x; a.y += v.y; a.z += v.z; a.w += v.w;
}
__device__ __forceinline__ float4 blend2(float4 p, float wp, float4 q, float wq) {
    float4 r;
    r.x = p.x * wp + q.x * wq;
    r.y = p.y * wp + q.y * wq;
    r.z = p.z * wp + q.z * wq;
    r.w = p.w * wp + q.w * wq;
    return r;
}
__device__ __forceinline__ uint2 pack_h4(float4 v) {
    __half2 lo = __floats2half2_rn(v.x, v.y);
    __half2 hi = __floats2half2_rn(v.z, v.w);
    uint2 u;
    u.x = *reinterpret_cast<unsigned int*>(&lo);
    u.y = *reinterpret_cast<unsigned int*>(&hi);
    return u;
}
__device__ __forceinline__ float4 unpack_h4(uint2 u) {
    __half2 lo = *reinterpret_cast<__half2*>(&u.x);
    __half2 hi = *reinterpret_cast<__half2*>(&u.y);
    float2 a = __half22float2(lo);
    float2 b = __half22float2(hi);
    return make_float4(a.x, a.y, b.x, b.y);
}

// ---------------------------------------------------------------------------
// K1: SAME avg-pool 6x6 stride 4 — barrier-free, smem-free.
// Two threads per pooled output: thread (c4, hl) sums x-cols
// [4ox-1+3hl .. 4ox+1+3hl] x 6 y-rows (18 guarded loads); halves combined
// with shfl_xor(16) (lanes 0-15 vs 16-31 hold the two halves of the same
// 16 c4 outputs). hl=0 lanes store the fp16 average.
// ---------------------------------------------------------------------------
__global__ __launch_bounds__(256) void pool_kernel(const float4* __restrict__ in4) {
    int tid = blockIdx.x * 256 + threadIdx.x;   // 1,048,576 total
    int c4 = tid & 15;
    int hl = (tid >> 4) & 1;
    int ox = (tid >> 5) & 63;
    int oy = (tid >> 11) & 63;
    int b  = tid >> 17;

    int xs = 4 * ox - 1 + 3 * hl;   // first of 3 x-columns for this half
    int r0 = 4 * oy - 1;

    const float4* base = in4 + ((size_t)b * HIN * WIN) * CV4 + c4;
    const size_t RS = (size_t)WIN * CV4;

    float4 s = make_float4(0.f, 0.f, 0.f, 0.f);
    bool yint = (oy != 0) && (oy != 63);
    bool xint = (xs >= 0) && (xs + 2 < 256);

    if (yint && xint) {
        const float4* p = base + ((size_t)r0 * WIN + xs) * CV4;
        // 3 batches of 6 loads (one y-row triplet per x)
        #pragma unroll
        for (int r = 0; r < 6; ++r) {
            float4 v0 = __ldg(p + (size_t)r * RS + 0 * CV4);
            float4 v1 = __ldg(p + (size_t)r * RS + 1 * CV4);
            float4 v2 = __ldg(p + (size_t)r * RS + 2 * CV4);
            acc4(s, v0); acc4(s, v1); acc4(s, v2);
        }
    } else {
        #pragma unroll
        for (int r = 0; r < 6; ++r) {
            int rr = r0 + r;
            if ((unsigned)rr < 256u) {
                #pragma unroll
                for (int dx = 0; dx < 3; ++dx) {
                    int x = xs + dx;
                    if ((unsigned)x < 256u)
                        acc4(s, __ldg(base + ((size_t)rr * WIN + x) * CV4));
                }
            }
        }
    }

    // combine the two x-halves (lane ^ 16)
    float4 w;
    w.x = s.x + __shfl_xor_sync(0xffffffffu, s.x, 16);
    w.y = s.y + __shfl_xor_sync(0xffffffffu, s.y, 16);
    w.z = s.z + __shfl_xor_sync(0xffffffffu, s.z, 16);
    w.w = s.w + __shfl_xor_sync(0xffffffffu, s.w, 16);

    if (hl == 0) {
        int nr = 6 - (oy == 0) - (oy == 63);
        int nc = 6 - (ox == 0) - (ox == 63);
        float inv = 1.0f / (float)(nr * nc);
        g_pooled[(((size_t)b * HP + oy) * WP + ox) * CV4 + c4] =
            pack_h4(make_float4(w.x * inv, w.y * inv, w.z * inv, w.w * inv));
    }
}

// ---------------------------------------------------------------------------
// K2: unaverage pool (x4 upsample), direct streaming — byte-identical to the
// R9-proven 22.6us version (fp16 taps).
// ---------------------------------------------------------------------------
__device__ __forceinline__ float d2s(float d) {
    if (d < 5.5f)   return (d - 2.0f) * (1.0f / 3.5f);
    if (d > 249.5f) return (d - 249.5f) * (1.0f / 3.5f) + 62.0f;
    return (d - 1.5f) * 0.25f;
}

__global__ __launch_bounds__(256, 6) void up_kernel(float4* __restrict__ out4) {
    int tid = blockIdx.x * 256 + threadIdx.x;   // B*256*32*16 = 1,048,576
    int c4 = tid & 15;
    int kk = (tid >> 4) & 31;
    int y  = (tid >> 9) & 255;
    int b  = tid >> 17;

    int k0 = kk * 2;

    float sr  = d2s((float)y);
    float r0f = floorf(sr);
    int   r0  = (int)r0f;
    float fr  = sr - r0f;
    bool rv0 = (r0 >= 0);
    bool rv1 = (r0 < HP - 1);
    float wr0 = 1.0f - fr;

    const uint2* pbase = g_pooled + ((size_t)b * HP * WP) * CV4 + c4;
    const uint2* rowA  = pbase + (size_t)(rv0 ? r0     : 0) * WP * CV4;
    const uint2* rowB  = pbase + (size_t)(rv1 ? r0 + 1 : 0) * WP * CV4;

    const float4 z = make_float4(0.f, 0.f, 0.f, 0.f);

    float4 T[4];
    #pragma unroll
    for (int i = 0; i < 4; ++i) {
        int col = k0 - 1 + i;
        bool cv = (unsigned)col < (unsigned)WP;
        float4 a  = (rv0 && cv) ? unpack_h4(__ldg(rowA + (size_t)col * CV4)) : z;
        float4 bb = (rv1 && cv) ? unpack_h4(__ldg(rowB + (size_t)col * CV4)) : z;
        T[i] = blend2(a, wr0, bb, fr);
    }

    float4* op = out4 + (((size_t)b * HIN + y) * WIN + k0 * 4) * CV4 + c4;

    if (kk >= 1 && kk <= 30) {
        op[0 * CV4] = blend2(T[0], 0.375f, T[1], 0.625f);
        op[1 * CV4] = blend2(T[0], 0.125f, T[1], 0.875f);
        op[2 * CV4] = blend2(T[1], 0.875f, T[2], 0.125f);
        op[3 * CV4] = blend2(T[1], 0.625f, T[2], 0.375f);
        op[4 * CV4] = blend2(T[1], 0.375f, T[2], 0.625f);
        op[5 * CV4] = blend2(T[1], 0.125f, T[2], 0.875f);
        op[6 * CV4] = blend2(T[2], 0.875f, T[3], 0.125f);
        op[7 * CV4] = blend2(T[2], 0.625f, T[3], 0.375f);
    } else {
        int x0 = k0 * 4;
        #pragma unroll
        for (int m = 0; m < 8; ++m) {
            float sc  = d2s((float)(x0 + m));
            float c0f = floorf(sc);
            float fc  = sc - c0f;
            int idx = (int)c0f - (k0 - 1);   // 0..2
            float4 lo = (idx == 0) ? T[0] : ((idx == 1) ? T[1] : T[2]);
            float4 hi = (idx == 0) ? T[1] : ((idx == 1) ? T[2] : T[3]);
            op[m * CV4] = blend2(lo, 1.0f - fc, hi, fc);
        }
    }
}

extern "C" void kernel_launch(void* const* d_in, const int* in_sizes, int n_in,
                              void* d_out, int out_size) {
    const float4* in4 = (const float4*)d_in[0];
    float4* out4 = (float4*)d_out;

    pool_kernel<<<4096, 256>>>(in4);                      // 2 threads/output
    up_kernel<<<(B * HIN * 32 * CV4) / 256, 256>>>(out4); // 4096 CTAs
}

// round 14
// speedup vs baseline: 1.0643x; 1.0643x over previous
#include <cuda_runtime.h>
#include <cuda_fp16.h>
#include <cuda_bf16.h>

// Problem constants
#define B    8
#define HIN  256
#define WIN  256
#define CV4  16      // C/4 channel chunks per pixel (C=64)
#define HP   64
#define WP   64

// 4 MB pooled averages in fp16 — static device scratch
__device__ uint2 g_pooled[B * HP * WP * CV4];

__device__ __forceinline__ void acc4(float4& a, const float4 v) {
    a.x += v.x; a.y += v.y; a.z += v.z; a.w += v.w;
}
__device__ __forceinline__ float4 blend2(float4 p, float wp, float4 q, float wq) {
    float4 r;
    r.x = p.x * wp + q.x * wq;
    r.y = p.y * wp + q.y * wq;
    r.z = p.z * wp + q.z * wq;
    r.w = p.w * wp + q.w * wq;
    return r;
}
__device__ __forceinline__ uint2 pack_h4(float4 v) {
    __half2 lo = __floats2half2_rn(v.x, v.y);
    __half2 hi = __floats2half2_rn(v.z, v.w);
    uint2 u;
    u.x = *reinterpret_cast<unsigned int*>(&lo);
    u.y = *reinterpret_cast<unsigned int*>(&hi);
    return u;
}
__device__ __forceinline__ float4 unpack_h4(uint2 u) {
    __half2 lo = *reinterpret_cast<__half2*>(&u.x);
    __half2 hi = *reinterpret_cast<__half2*>(&u.y);
    float2 a = __half22float2(lo);
    float2 b = __half22float2(hi);
    return make_float4(a.x, a.y, b.x, b.y);
}

// ---------------------------------------------------------------------------
// K1: fused SAME avg-pool 6x6 stride 4 (R12 geometry, MLP-fixed phase 1).
// CTA = (b, oy, x-group g of 16 ox), 256 threads, grid 2048.
// Phase 1: 1056 column-sum tasks; each thread runs 4 statically-unrolled
//          independent task bodies (+1 guarded) so all ~24 loads batch.
// Phase 2: one output/thread: 6 LDS.128 + divide, fp16 store.
// ---------------------------------------------------------------------------
#define GSPAN 66
#define NT1   (GSPAN * CV4)    // 1056

__device__ __forceinline__ float4 colsum6(const float4* __restrict__ p, size_t RS) {
    float4 a0 = __ldg(p + 0 * RS);
    float4 a1 = __ldg(p + 1 * RS);
    float4 a2 = __ldg(p + 2 * RS);
    float4 a3 = __ldg(p + 3 * RS);
    float4 a4 = __ldg(p + 4 * RS);
    float4 a5 = __ldg(p + 5 * RS);
    float4 s;
    s.x = ((a0.x + a1.x) + (a2.x + a3.x)) + (a4.x + a5.x);
    s.y = ((a0.y + a1.y) + (a2.y + a3.y)) + (a4.y + a5.y);
    s.z = ((a0.z + a1.z) + (a2.z + a3.z)) + (a4.z + a5.z);
    s.w = ((a0.w + a1.w) + (a2.w + a3.w)) + (a4.w + a5.w);
    return s;
}

__global__ __launch_bounds__(256, 4) void pool_kernel(const float4* __restrict__ in4) {
    __shared__ float4 cs[NT1];

    int bid = blockIdx.x;      // ((b*64)+oy)*4 + g
    int g  = bid & 3;
    int oy = (bid >> 2) & 63;
    int b  = bid >> 8;

    int t = threadIdx.x;
    int r0 = 4 * oy - 1;
    bool yint = (oy != 0) && (oy != 63);
    int xbase = 64 * g - 1;

    const float4* base = in4 + ((size_t)b * HIN * WIN) * CV4;
    const size_t RS = (size_t)WIN * CV4;

    if (yint) {
        // interior y: all 6 rows valid; 4 independent task bodies batch loads
        #pragma unroll
        for (int it = 0; it < 4; ++it) {
            int v  = t + it * 256;
            int c4 = v & 15;
            int xl = v >> 4;
            int x  = xbase + xl;
            float4 s = make_float4(0.f, 0.f, 0.f, 0.f);
            if ((unsigned)x < 256u)
                s = colsum6(base + ((size_t)r0 * WIN + x) * CV4 + c4, RS);
            cs[v] = s;
        }
        if (t < 32) {
            int v  = t + 1024;
            int c4 = v & 15;
            int xl = v >> 4;
            int x  = xbase + xl;
            float4 s = make_float4(0.f, 0.f, 0.f, 0.f);
            if ((unsigned)x < 256u)
                s = colsum6(base + ((size_t)r0 * WIN + x) * CV4 + c4, RS);
            cs[v] = s;
        }
    } else {
        // edge y (oy = 0 or 63): 5 valid rows, per-row guard
        #pragma unroll 1
        for (int v = t; v < NT1; v += 256) {
            int c4 = v & 15;
            int xl = v >> 4;
            int x  = xbase + xl;
            float4 s = make_float4(0.f, 0.f, 0.f, 0.f);
            if ((unsigned)x < 256u) {
                const float4* p = base + (size_t)x * CV4 + c4;
                #pragma unroll
                for (int j = 0; j < 6; ++j) {
                    int r = r0 + j;
                    if ((unsigned)r < 256u)
                        acc4(s, __ldg(p + (size_t)r * RS));
                }
            }
            cs[v] = s;
        }
    }
    __syncthreads();

    // Phase 2: exactly one output per thread
    {
        int c4  = t & 15;
        int oxl = t >> 4;          // 0..15
        int ox  = 16 * g + oxl;

        float4 s = make_float4(0.f, 0.f, 0.f, 0.f);
        if (ox != 0) acc4(s, cs[(4 * oxl + 0) * CV4 + c4]);
        acc4(s, cs[(4 * oxl + 1) * CV4 + c4]);
        acc4(s, cs[(4 * oxl + 2) * CV4 + c4]);
        acc4(s, cs[(4 * oxl + 3) * CV4 + c4]);
        acc4(s, cs[(4 * oxl + 4) * CV4 + c4]);
        if (ox != 63) acc4(s, cs[(4 * oxl + 5) * CV4 + c4]);

        int nr = 6 - (oy == 0) - (oy == 63);
        int nc = 6 - (ox == 0) - (ox == 63);
        float inv = 1.0f / (float)(nr * nc);
        g_pooled[(((size_t)b * HP + oy) * WP + ox) * CV4 + c4] =
            pack_h4(make_float4(s.x * inv, s.y * inv, s.z * inv, s.w * inv));
    }
}

// ---------------------------------------------------------------------------
// K2: unaverage pool (x4 upsample), direct streaming — byte-identical to the
// R9-proven 22.6us version (fp16 taps).
// ---------------------------------------------------------------------------
__device__ __forceinline__ float d2s(float d) {
    if (d < 5.5f)   return (d - 2.0f) * (1.0f / 3.5f);
    if (d > 249.5f) return (d - 249.5f) * (1.0f / 3.5f) + 62.0f;
    return (d - 1.5f) * 0.25f;
}

__global__ __launch_bounds__(256, 6) void up_kernel(float4* __restrict__ out4) {
    int tid = blockIdx.x * 256 + threadIdx.x;   // B*256*32*16 = 1,048,576
    int c4 = tid & 15;
    int kk = (tid >> 4) & 31;
    int y  = (tid >> 9) & 255;
    int b  = tid >> 17;

    int k0 = kk * 2;

    float sr  = d2s((float)y);
    float r0f = floorf(sr);
    int   r0  = (int)r0f;
    float fr  = sr - r0f;
    bool rv0 = (r0 >= 0);
    bool rv1 = (r0 < HP - 1);
    float wr0 = 1.0f - fr;

    const uint2* pbase = g_pooled + ((size_t)b * HP * WP) * CV4 + c4;
    const uint2* rowA  = pbase + (size_t)(rv0 ? r0     : 0) * WP * CV4;
    const uint2* rowB  = pbase + (size_t)(rv1 ? r0 + 1 : 0) * WP * CV4;

    const float4 z = make_float4(0.f, 0.f, 0.f, 0.f);

    float4 T[4];
    #pragma unroll
    for (int i = 0; i < 4; ++i) {
        int col = k0 - 1 + i;
        bool cv = (unsigned)col < (unsigned)WP;
        float4 a  = (rv0 && cv) ? unpack_h4(__ldg(rowA + (size_t)col * CV4)) : z;
        float4 bb = (rv1 && cv) ? unpack_h4(__ldg(rowB + (size_t)col * CV4)) : z;
        T[i] = blend2(a, wr0, bb, fr);
    }

    float4* op = out4 + (((size_t)b * HIN + y) * WIN + k0 * 4) * CV4 + c4;

    if (kk >= 1 && kk <= 30) {
        op[0 * CV4] = blend2(T[0], 0.375f, T[1], 0.625f);
        op[1 * CV4] = blend2(T[0], 0.125f, T[1], 0.875f);
        op[2 * CV4] = blend2(T[1], 0.875f, T[2], 0.125f);
        op[3 * CV4] = blend2(T[1], 0.625f, T[2], 0.375f);
        op[4 * CV4] = blend2(T[1], 0.375f, T[2], 0.625f);
        op[5 * CV4] = blend2(T[1], 0.125f, T[2], 0.875f);
        op[6 * CV4] = blend2(T[2], 0.875f, T[3], 0.125f);
        op[7 * CV4] = blend2(T[2], 0.625f, T[3], 0.375f);
    } else {
        int x0 = k0 * 4;
        #pragma unroll
        for (int m = 0; m < 8; ++m) {
            float sc  = d2s((float)(x0 + m));
            float c0f = floorf(sc);
            float fc  = sc - c0f;
            int idx = (int)c0f - (k0 - 1);   // 0..2
            float4 lo = (idx == 0) ? T[0] : ((idx == 1) ? T[1] : T[2]);
            float4 hi = (idx == 0) ? T[1] : ((idx == 1) ? T[2] : T[3]);
            op[m * CV4] = blend2(lo, 1.0f - fc, hi, fc);
        }
    }
}

extern "C" void kernel_launch(void* const* d_in, const int* in_sizes, int n_in,
                              void* d_out, int out_size) {
    const float4* in4 = (const float4*)d_in[0];
    float4* out4 = (float4*)d_out;

    pool_kernel<<<B * HP * 4, 256>>>(in4);                // 2048 CTAs
    up_kernel<<<(B * HIN * 32 * CV4) / 256, 256>>>(out4); // 4096 CTAs
}